// round 8
// baseline (speedup 1.0000x reference)
#include <cuda_runtime.h>

// rosa_emb_layer: B=8, T=2048, V=50257, C=768
// inputs: d_in[0] = idx (B,T) int32, d_in[1] = emb (V,C) float32
// output: (B,T,C) float32
//
// R7: traffic model says R1 saturates TOTAL LTS (~5.6 TB/s) and wastes
// 16MB/66MB of it on per-CTA smem fills of the idx row. Delete the smem
// copy: read idx straight through L1 (__ldg). L1 persists within-launch;
// whole idx table is 64KB -> near-total L1 hit rate after warmup, L2 idx
// reads drop ~16MB -> <1MB. No fill, no syncthreads, no smem.
// Keep: one warp per row, phase-0 optimistic zero stores (overlap drain),
// (L<<11)|j packed max == argmax(L + j*1e-5) with larger-j tie-break,
// v8 ld/st for the rare matched-row fixup.

#define TT 2048
#define BB 8
#define CC 768
#define WPB 8  // warps per CTA

__device__ __forceinline__ void stg_v8(float* p,
                                       float a, float b, float c, float d,
                                       float e, float f, float g, float h) {
    asm volatile("st.global.v8.f32 [%0], {%1,%2,%3,%4,%5,%6,%7,%8};"
                 :: "l"(p), "f"(a), "f"(b), "f"(c), "f"(d),
                    "f"(e), "f"(f), "f"(g), "f"(h) : "memory");
}

__device__ __forceinline__ void ldg_v8(const float* p, float* r) {
    asm volatile("ld.global.nc.v8.f32 {%0,%1,%2,%3,%4,%5,%6,%7}, [%8];"
                 : "=f"(r[0]), "=f"(r[1]), "=f"(r[2]), "=f"(r[3]),
                   "=f"(r[4]), "=f"(r[5]), "=f"(r[6]), "=f"(r[7])
                 : "l"(p));
}

__global__ __launch_bounds__(256, 8)
void rosa_emb_kernel(const int* __restrict__ idx,
                     const float* __restrict__ emb,
                     float* __restrict__ out) {
    const int cta_per_b = TT / WPB;               // 256
    const int b      = blockIdx.x / cta_per_b;
    const int i_base = (blockIdx.x % cta_per_b) * WPB;
    const int tid  = threadIdx.x;
    const int w    = tid >> 5;
    const int lane = tid & 31;
    const int i    = i_base + w;

    // ---- Phase 0: fire this warp's zero row immediately (no deps). ----
    float* orow = out + ((size_t)b * TT + i) * CC;
    #pragma unroll
    for (int k = 0; k < 3; k++)
        stg_v8(orow + (lane + 32 * k) * 8,
               0.f, 0.f, 0.f, 0.f, 0.f, 0.f, 0.f, 0.f);

    // ---- Phase 1: compare scan, idx read straight through L1. ----
    const int*  xb = idx + (size_t)b * TT;
    const int4* x4 = (const int4*)xb;
    const int   xi = __ldg(xb + i);

    // best = (L << 11) | j  (L in [1,2048], j in [0,2047]); 0 == no match.
    int best = 0;

    // Lanes cover j in [0, i) with int4 chunks: lane -> j0 = 4*lane + 128*k.
    for (int j0 = lane * 4; j0 < i; j0 += 128) {
        const int4 v = __ldg(x4 + (j0 >> 2));
        const bool m0 = (v.x == xi);                    // j0 < i guaranteed
        const bool m1 = (v.y == xi) & (j0 + 1 < i);
        const bool m2 = (v.z == xi) & (j0 + 2 < i);
        const bool m3 = (v.w == xi) & (j0 + 3 < i);
        if (m0 | m1 | m2 | m3) {                        // rare (~1/12500 per elt)
            #pragma unroll
            for (int c = 0; c < 4; c++) {
                const bool m = (c == 0) ? m0 : (c == 1) ? m1 : (c == 2) ? m2 : m3;
                if (m) {
                    const int j = j0 + c;
                    int L = 1, t = 1;
                    while (t <= j && __ldg(xb + i - t) == __ldg(xb + j - t)) { ++L; ++t; }
                    const int packed = (L << 11) | j;
                    if (packed > best) best = packed;
                }
            }
        }
    }

    // Warp max-reduce the packed (L, j) score.
    #pragma unroll
    for (int o = 16; o; o >>= 1)
        best = max(best, __shfl_xor_sync(0xffffffffu, best, o));

    // ---- Phase 2 (rare): overwrite matched row with emb data. Same lanes
    // rewrite the same addresses they zeroed -> per-thread order holds. ----
    if (best >= (1 << 11)) {
        const int bj = best & 2047;
        int pidx = bj + 1; if (pidx > TT - 1) pidx = TT - 1;
        const int tok = __ldg(xb + pidx);
        const float* erow = emb + (size_t)tok * CC;
        float r[24];
        #pragma unroll
        for (int k = 0; k < 3; k++)
            ldg_v8(erow + (lane + 32 * k) * 8, r + 8 * k);
        #pragma unroll
        for (int k = 0; k < 3; k++)
            stg_v8(orow + (lane + 32 * k) * 8,
                   r[8*k], r[8*k+1], r[8*k+2], r[8*k+3],
                   r[8*k+4], r[8*k+5], r[8*k+6], r[8*k+7]);
    }
}

extern "C" void kernel_launch(void* const* d_in, const int* in_sizes, int n_in,
                              void* d_out, int out_size) {
    const int*   idx = (const int*)d_in[0];
    const float* emb = (const float*)d_in[1];
    float*       out = (float*)d_out;

    rosa_emb_kernel<<<BB * (TT / WPB), 256>>>(idx, emb, out);
}